// round 9
// baseline (speedup 1.0000x reference)
#include <cuda_runtime.h>
#include <cstdint>

#define N_OUT_C 50000
#define KNN 32
#define CIN 16
#define COUT 32
#define KC 1024
#define NWARP 8
#define GROUP 16
#define NGROUPS (N_OUT_C / GROUP)   // 3125
#define PSTRIDE 2056                // floats per pair region (2048 + 8 pad)

struct __align__(16) Smem {
    float  B[NWARP * PSTRIDE];      // 65792 B, pair-interleaved [kc][2] per warp
    float4 meta4[NWARP][2][KNN];    // 8192 B
    int    packs[NWARP][2][KNN];    // 2048 B
    float  acc[4][16][34];          // 8704 B: partial sums (rows x cols, padded)
    float  dens[2][GROUP];          // 128 B, parity double-buffered
};
// total 84864 B -> 2 CTAs/SM

__device__ __forceinline__ uint32_t f2tf32(float x) {
    uint32_t r;
    asm("cvt.rna.tf32.f32 %0, %1;" : "=r"(r) : "f"(x));
    return r;
}
__device__ __forceinline__ void mma_tf32(float* d, uint32_t a0, uint32_t a1,
                                         uint32_t a2, uint32_t a3,
                                         uint32_t b0, uint32_t b1) {
    asm volatile(
        "mma.sync.aligned.m16n8k8.row.col.f32.tf32.tf32.f32 "
        "{%0,%1,%2,%3},{%4,%5,%6,%7},{%8,%9},{%0,%1,%2,%3};"
        : "+f"(d[0]), "+f"(d[1]), "+f"(d[2]), "+f"(d[3])
        : "r"(a0), "r"(a1), "r"(a2), "r"(a3), "r"(b0), "r"(b1));
}

__global__ __launch_bounds__(256, 2)
void cconv_fused(const float* __restrict__ feats,
                 const float* __restrict__ inp_points,
                 const float* __restrict__ out_points,
                 const float* __restrict__ out_extents,
                 const float* __restrict__ scale_compat,
                 const int*   __restrict__ nidx,
                 const float* __restrict__ ndist,
                 const float* __restrict__ kernW,
                 const float* __restrict__ bias,
                 float* __restrict__ out)
{
    extern __shared__ unsigned char raw[];
    Smem* S = reinterpret_cast<Smem*>(raw);
    const int tid = threadIdx.x, wid = tid >> 5, lane = tid & 31;
    const int fg = lane >> 2, ft = lane & 3;    // MMA fragment coords

    int par = 0;
    for (int grp = blockIdx.x; grp < NGROUPS; grp += gridDim.x, par ^= 1) {
        const int gbase = grp * GROUP;
        const int obase = gbase + wid * 2;

        // ============ Phase A: zero B, geometry, scatter (warp-private) ======
        {
            float4* Bz = reinterpret_cast<float4*>(S->B + wid * PSTRIDE);
            #pragma unroll
            for (int z = 0; z < 16; z++)
                Bz[z * 32 + lane] = make_float4(0.f, 0.f, 0.f, 0.f);
        }

        #pragma unroll
        for (int s = 0; s < 2; s++) {           // lane = edge
            const int o = obase + s;
            const int eid = o * KNN + lane;
            const int nbr = nidx[eid];
            const float dist = ndist[eid];
            const float sc = scale_compat[eid];
            float tt = 1.f - dist * dist;
            float win = fminf(fmaxf(tt * tt * tt, 0.f), 1.f);
            const float imp = sc * win;

            const float pix = inp_points[nbr * 3 + 0];
            const float piy = inp_points[nbr * 3 + 1];
            const float piz = inp_points[nbr * 3 + 2];
            const float inv = __fdividef(2.f, out_extents[o]);
            const float rx = (pix - out_points[o * 3 + 0]) * inv;
            const float ry = (piy - out_points[o * 3 + 1]) * inv;
            const float rz = (piz - out_points[o * 3 + 2]) * inv;

            const float r = sqrtf(rx * rx + ry * ry + rz * rz);
            const float linf = fmaxf(fabsf(rx), fmaxf(fabsf(ry), fabsf(rz)));
            const float sf = __fdividef(r, fmaxf(linf, 1e-12f));
            float tx = fminf(fmaxf((rx * sf * 0.5f + 0.5f) * 3.f, 0.f), 3.f);
            float ty = fminf(fmaxf((ry * sf * 0.5f + 0.5f) * 3.f, 0.f), 3.f);
            float tz = fminf(fmaxf((rz * sf * 0.5f + 0.5f) * 3.f, 0.f), 3.f);
            float t0x = fminf(floorf(tx), 2.f);
            float t0y = fminf(floorf(ty), 2.f);
            float t0z = fminf(floorf(tz), 2.f);
            int ix = (int)t0x, iy = (int)t0y, iz = (int)t0z;

            S->meta4[wid][s][lane] = make_float4(tx - t0x, ty - t0y, tz - t0z, imp);
            S->packs[wid][s][lane] = nbr | (ix << 20) | (iy << 22) | (iz << 24);

            float dsum = imp;
            #pragma unroll
            for (int off = 16; off; off >>= 1)
                dsum += __shfl_xor_sync(0xffffffffu, dsum, off);
            if (lane == 0) S->dens[par][wid * 2 + s] = dsum;
        }
        __syncwarp();

        {   // scatter: half-warp h -> slot h; bank = (2c+h)%32, conflict-free
            const int h = lane >> 4, c = lane & 15;
            float* Bw = S->B + wid * PSTRIDE;
            const float4* m4 = S->meta4[wid][h];
            const int* pk = S->packs[wid][h];
            #pragma unroll 4
            for (int e = 0; e < KNN; e++) {
                const float4 m = m4[e];
                const int p = pk[e];
                const int nb = p & 0xFFFFF;
                const int ix = (p >> 20) & 3, iy = (p >> 22) & 3, iz = (p >> 24) & 3;
                const float fe = __ldg(&feats[nb * CIN + c]) * m.w;
                const float ax1 = fe * m.x, ax0 = fe - ax1;
                const float v01 = ax0 * m.y, v00 = ax0 - v01;
                const float v11 = ax1 * m.y, v10 = ax1 - v11;
                const float wz1 = m.z, wz0 = 1.f - m.z;
                float* Bp = Bw + ((ix * 16 + iy * 4 + iz) * 32 + c * 2 + h);
                Bp[0]   += v00 * wz0;  Bp[32]  += v00 * wz1;
                Bp[128] += v01 * wz0;  Bp[160] += v01 * wz1;
                Bp[512] += v10 * wz0;  Bp[544] += v10 * wz1;
                Bp[640] += v11 * wz0;  Bp[672] += v11 * wz1;
            }
        }
        __syncthreads();

        // ============ Phase B: tf32 MMA, warp owns K-slice [wid*128, +128) ====
        // A rows: r in 0..15 -> pair (r&7), half (r>>3); offset (r&7)*PSTRIDE
        //   + kc*2 + (r>>3).  a0/a1 and a2/a3 are adjacent -> LDS.64.
        float cc[4][4];
        #pragma unroll
        for (int nb = 0; nb < 4; nb++)
            #pragma unroll
            for (int i = 0; i < 4; i++) cc[nb][i] = 0.f;

        const float* Arow = S->B + fg * PSTRIDE;
        #pragma unroll 2
        for (int q = 0; q < 16; q++) {
            const int k = wid * 128 + q * 8;
            const float2 A01 = *reinterpret_cast<const float2*>(Arow + 2 * (k + ft));
            const float2 A23 = *reinterpret_cast<const float2*>(Arow + 2 * (k + ft + 4));
            const uint32_t a0 = f2tf32(A01.x), a1 = f2tf32(A01.y);
            const uint32_t a2 = f2tf32(A23.x), a3 = f2tf32(A23.y);
            #pragma unroll
            for (int nb = 0; nb < 4; nb++) {
                const float w0 = __ldg(&kernW[(k + ft) * COUT + nb * 8 + fg]);
                const float w1 = __ldg(&kernW[(k + ft + 4) * COUT + nb * 8 + fg]);
                const uint32_t b0h = f2tf32(w0);
                const uint32_t b1h = f2tf32(w1);
                const uint32_t b0l = f2tf32(w0 - __uint_as_float(b0h));
                const uint32_t b1l = f2tf32(w1 - __uint_as_float(b1h));
                mma_tf32(cc[nb], a0, a1, a2, a3, b0h, b1h);
                mma_tf32(cc[nb], a0, a1, a2, a3, b0l, b1l);
            }
        }

        // ============ Phase C: combine partials across warps =================
        if (wid < 4) {
            float* ap = &S->acc[wid][0][0];
            #pragma unroll
            for (int nb = 0; nb < 4; nb++) {
                *reinterpret_cast<float2*>(ap + fg * 34 + nb * 8 + 2 * ft) =
                    make_float2(cc[nb][0], cc[nb][1]);
                *reinterpret_cast<float2*>(ap + (fg + 8) * 34 + nb * 8 + 2 * ft) =
                    make_float2(cc[nb][2], cc[nb][3]);
            }
        }
        __syncthreads();
        if (wid >= 4) {
            float* ap = &S->acc[wid - 4][0][0];
            #pragma unroll
            for (int nb = 0; nb < 4; nb++) {
                float2* p0 = reinterpret_cast<float2*>(ap + fg * 34 + nb * 8 + 2 * ft);
                float2* p1 = reinterpret_cast<float2*>(ap + (fg + 8) * 34 + nb * 8 + 2 * ft);
                float2 v0 = *p0, v1 = *p1;
                v0.x += cc[nb][0]; v0.y += cc[nb][1];
                v1.x += cc[nb][2]; v1.y += cc[nb][3];
                *p0 = v0; *p1 = v1;
            }
        }
        __syncthreads();

        // ============ Phase D: epilogue (reduce 4, normalize, bias, relu) ====
        {
            const int r = tid >> 4;                 // 0..15 row
            const int nc = (tid & 15) * 2;          // even col
            float2 s = make_float2(0.f, 0.f);
            #pragma unroll
            for (int q = 0; q < 4; q++) {
                float2 v = *reinterpret_cast<const float2*>(&S->acc[q][r][nc]);
                s.x += v.x; s.y += v.y;
            }
            const int widx = 2 * (r & 7) + (r >> 3);
            const int o = gbase + widx;
            float dn = S->dens[par][widx];
            const float inv = __fdividef(1.f, dn > 0.f ? dn : 1.f);
            const float2 bb = *reinterpret_cast<const float2*>(bias + nc);
            float2 v;
            v.x = fmaxf(s.x * inv + bb.x, 0.f);
            v.y = fmaxf(s.y * inv + bb.y, 0.f);
            *reinterpret_cast<float2*>(out + (size_t)o * COUT + nc) = v;
        }
    }
}

extern "C" void kernel_launch(void* const* d_in, const int* in_sizes, int n_in,
                              void* d_out, int out_size)
{
    const float* feats        = (const float*)d_in[0];
    const float* inp_points   = (const float*)d_in[1];
    const float* out_points   = (const float*)d_in[2];
    const float* out_extents  = (const float*)d_in[3];
    const float* scale_compat = (const float*)d_in[4];
    const int*   nidx         = (const int*)  d_in[5];
    // d_in[6] = neighbors_row_splits: fixed degree, unused
    const float* ndist        = (const float*)d_in[7];
    const float* kernW        = (const float*)d_in[8];
    const float* bias         = (const float*)d_in[9];
    float* out = (float*)d_out;

    cudaFuncSetAttribute(cconv_fused, cudaFuncAttributeMaxDynamicSharedMemorySize,
                         (int)sizeof(Smem));
    cconv_fused<<<296, 256, sizeof(Smem)>>>(feats, inp_points, out_points,
                                            out_extents, scale_compat, nidx,
                                            ndist, kernW, bias, out);
}

// round 10
// speedup vs baseline: 1.3349x; 1.3349x over previous
#include <cuda_runtime.h>
#include <cuda_fp16.h>
#include <cstdint>

#define N_OUT_C 50000
#define KNN 32
#define CIN 16
#define COUT 32
#define KC 1024
#define MTILE2 64
#define NTILES2 784             // 784*64 = 50176 >= 50000

// ============== device scratch (static, zero-init, no allocations) ==========
__device__ __half g_B16[(size_t)50176 * KC];      // 102.8 MB row-major fp16
__device__ uint4  g_Wfrag[64 * 4 * 32];           // [k16][nb][lane] = b0h,b1h,b0l,b1l
__device__ float  g_den[N_OUT_C];

__device__ __forceinline__ uint32_t smem_u32(const void* p) {
    uint32_t a;
    asm("{ .reg .u64 t; cvta.to.shared.u64 t, %1; cvt.u32.u64 %0, t; }"
        : "=r"(a) : "l"(p));
    return a;
}
__device__ __forceinline__ uint32_t packh2(__half a, __half b) {
    __half2 h = __halves2half2(a, b);
    return *reinterpret_cast<uint32_t*>(&h);
}

// ====== K0: pre-pack W into per-lane mma B-fragments (hi/lo planes) ========
__global__ void k0_wfrag(const float* __restrict__ kernW) {
    int i = blockIdx.x * 256 + threadIdx.x;       // 8192 total
    if (i >= 64 * 4 * 32) return;
    int k16 = i >> 7, r = i & 127, nb = r >> 5, lane = r & 31;
    int t = lane & 3, g = lane >> 2, n = nb * 8 + g;
    int kb = k16 * 16 + 2 * t;
    float w00 = kernW[(kb + 0) * COUT + n];
    float w01 = kernW[(kb + 1) * COUT + n];
    float w10 = kernW[(kb + 8) * COUT + n];
    float w11 = kernW[(kb + 9) * COUT + n];
    __half h00 = __float2half_rn(w00), h01 = __float2half_rn(w01);
    __half h10 = __float2half_rn(w10), h11 = __float2half_rn(w11);
    __half l00 = __float2half_rn(w00 - __half2float(h00));
    __half l01 = __float2half_rn(w01 - __half2float(h01));
    __half l10 = __float2half_rn(w10 - __half2float(h10));
    __half l11 = __float2half_rn(w11 - __half2float(h11));
    uint4 v;
    v.x = packh2(h00, h01);   // b0 hi
    v.y = packh2(h10, h11);   // b1 hi
    v.z = packh2(l00, l01);   // b0 lo
    v.w = packh2(l10, l11);   // b1 lo
    g_Wfrag[i] = v;
}

// ============== K1: geometry + conflict-free scatter + fp16 writeout ========
#define NW1 4
#define GROUP1 8
#define NGROUPS1 (N_OUT_C / GROUP1)   // 6250

struct __align__(16) Smem1 {
    float  B[NW1][KC * 2];        // 32768 B, pair-interleaved [kc][2 outs]
    float4 meta4[NW1][2][KNN];    // 4096 B
    int    packs[NW1][2][KNN];    // 1024 B
};                                // 37888 B -> 6 CTAs/SM

__global__ __launch_bounds__(128, 6)
void k1_scatter(const float* __restrict__ feats,
                const float* __restrict__ inp_points,
                const float* __restrict__ out_points,
                const float* __restrict__ out_extents,
                const float* __restrict__ scale_compat,
                const int*   __restrict__ nidx,
                const float* __restrict__ ndist)
{
    extern __shared__ unsigned char raw1[];
    Smem1* S = reinterpret_cast<Smem1*>(raw1);
    const int tid = threadIdx.x, wid = tid >> 5, lane = tid & 31;

    for (int g = blockIdx.x; g < NGROUPS1; g += gridDim.x) {
        const int obase = g * GROUP1 + wid * 2;

        {   // zero B
            float4* Bz = reinterpret_cast<float4*>(S->B[wid]);
            #pragma unroll
            for (int z = 0; z < 16; z++)
                Bz[z * 32 + lane] = make_float4(0.f, 0.f, 0.f, 0.f);
        }

        #pragma unroll
        for (int s = 0; s < 2; s++) {   // geometry, lane = edge
            const int o = obase + s;
            const int eid = o * KNN + lane;
            const int nbr = nidx[eid];
            const float dist = ndist[eid];
            const float sc = scale_compat[eid];
            float tt = 1.f - dist * dist;
            float win = fminf(fmaxf(tt * tt * tt, 0.f), 1.f);
            const float imp = sc * win;

            const float pix = inp_points[nbr * 3 + 0];
            const float piy = inp_points[nbr * 3 + 1];
            const float piz = inp_points[nbr * 3 + 2];
            const float inv = __fdividef(2.f, out_extents[o]);
            const float rx = (pix - out_points[o * 3 + 0]) * inv;
            const float ry = (piy - out_points[o * 3 + 1]) * inv;
            const float rz = (piz - out_points[o * 3 + 2]) * inv;

            const float r = sqrtf(rx * rx + ry * ry + rz * rz);
            const float linf = fmaxf(fabsf(rx), fmaxf(fabsf(ry), fabsf(rz)));
            const float sf = __fdividef(r, fmaxf(linf, 1e-12f));
            float tx = fminf(fmaxf((rx * sf * 0.5f + 0.5f) * 3.f, 0.f), 3.f);
            float ty = fminf(fmaxf((ry * sf * 0.5f + 0.5f) * 3.f, 0.f), 3.f);
            float tz = fminf(fmaxf((rz * sf * 0.5f + 0.5f) * 3.f, 0.f), 3.f);
            float t0x = fminf(floorf(tx), 2.f);
            float t0y = fminf(floorf(ty), 2.f);
            float t0z = fminf(floorf(tz), 2.f);
            int ix = (int)t0x, iy = (int)t0y, iz = (int)t0z;

            S->meta4[wid][s][lane] = make_float4(tx - t0x, ty - t0y, tz - t0z, imp);
            S->packs[wid][s][lane] = nbr | (ix << 20) | (iy << 22) | (iz << 24);

            float dsum = imp;
            #pragma unroll
            for (int off = 16; off; off >>= 1)
                dsum += __shfl_xor_sync(0xffffffffu, dsum, off);
            if (lane == 0) g_den[o] = dsum;
        }
        __syncwarp();

        {   // scatter: half-warp h -> slot h, bank (2c+h)%32 conflict-free
            const int h = lane >> 4, c = lane & 15;
            float* Bw = S->B[wid];
            const float4* m4 = S->meta4[wid][h];
            const int* pk = S->packs[wid][h];
            #pragma unroll 4
            for (int e = 0; e < KNN; e++) {
                const float4 m = m4[e];
                const int p = pk[e];
                const int nb = p & 0xFFFFF;
                const int ix = (p >> 20) & 3, iy = (p >> 22) & 3, iz = (p >> 24) & 3;
                const float fe = __ldg(&feats[nb * CIN + c]) * m.w;
                const float ax1 = fe * m.x, ax0 = fe - ax1;
                const float v01 = ax0 * m.y, v00 = ax0 - v01;
                const float v11 = ax1 * m.y, v10 = ax1 - v11;
                const float wz1 = m.z, wz0 = 1.f - m.z;
                float* Bp = Bw + ((ix * 16 + iy * 4 + iz) * 32 + c * 2 + h);
                Bp[0]   += v00 * wz0;  Bp[32]  += v00 * wz1;
                Bp[128] += v01 * wz0;  Bp[160] += v01 * wz1;
                Bp[512] += v10 * wz0;  Bp[544] += v10 * wz1;
                Bp[640] += v11 * wz0;  Bp[672] += v11 * wz1;
            }
        }
        __syncwarp();

        {   // writeout: row-major fp16, coalesced
            __half2* d0 = reinterpret_cast<__half2*>(g_B16 + (size_t)obase * KC);
            __half2* d1 = reinterpret_cast<__half2*>(g_B16 + (size_t)(obase + 1) * KC);
            const float4* Bq = reinterpret_cast<const float4*>(S->B[wid]);
            #pragma unroll 4
            for (int kt = 0; kt < 16; kt++) {
                float4 v = Bq[kt * 32 + lane];  // (kc,h0)(kc,h1)(kc+1,h0)(kc+1,h1)
                d0[kt * 32 + lane] = __floats2half2_rn(v.x, v.z);
                d1[kt * 32 + lane] = __floats2half2_rn(v.y, v.w);
            }
        }
        __syncwarp();
    }
}

// ======= K2: mma.sync fp16 GEMM, M=64/CTA, W-fragments from L2 ========
#define K2_A_STAGE (MTILE2 * 144)              // 9216 B (row stride 144 B)
#define K2_SMEM (2 * K2_A_STAGE)               // 18432 B -> ~6 CTAs/SM

__device__ __forceinline__ void ldsm_x4(uint32_t* a, uint32_t addr) {
    asm volatile("ldmatrix.sync.aligned.m8n8.x4.shared.b16 {%0,%1,%2,%3}, [%4];"
                 : "=r"(a[0]), "=r"(a[1]), "=r"(a[2]), "=r"(a[3]) : "r"(addr));
}
__device__ __forceinline__ void mma16816(float* d, const uint32_t* a,
                                         uint32_t b0, uint32_t b1) {
    asm volatile("mma.sync.aligned.m16n8k16.row.col.f32.f16.f16.f32 "
                 "{%0,%1,%2,%3}, {%4,%5,%6,%7}, {%8,%9}, {%0,%1,%2,%3};"
                 : "+f"(d[0]), "+f"(d[1]), "+f"(d[2]), "+f"(d[3])
                 : "r"(a[0]), "r"(a[1]), "r"(a[2]), "r"(a[3]), "r"(b0), "r"(b1));
}
__device__ __forceinline__ void cp16(uint32_t dst, const void* src) {
    asm volatile("cp.async.ca.shared.global [%0], [%1], 16;"
                 :: "r"(dst), "l"(src) : "memory");
}

__global__ __launch_bounds__(128, 6)
void k2_gemm(float* __restrict__ out, const float* __restrict__ bias)
{
    extern __shared__ unsigned char raw2[];
    const uint32_t sA = smem_u32(raw2);
    const int tid = threadIdx.x, w = tid >> 5, lane = tid & 31;
    const int g = lane >> 2, t = lane & 3;
    const int tile = blockIdx.x;
    const size_t abase = (size_t)tile * MTILE2 * KC;   // halfs

    // A chunk 0: 64 rows x 64 halfs (128 B), 512 x cp16 / 128 threads
    #pragma unroll
    for (int q = 0; q < 4; q++) {
        int idx = tid + q * 128;               // 0..511
        int row = idx >> 3, j = idx & 7;
        cp16(sA + row * 144 + j * 16,
             g_B16 + abase + (size_t)row * KC + j * 8);
    }
    asm volatile("cp.async.commit_group;" ::: "memory");

    float acc[4][4];
    #pragma unroll
    for (int nb = 0; nb < 4; nb++)
        #pragma unroll
        for (int i = 0; i < 4; i++) acc[nb][i] = 0.f;

    const uint32_t aBase = sA + (w * 16 + (lane & 15)) * 144 + (lane >> 4) * 16;

    for (int c = 0; c < 16; c++) {
        if (c < 15) {
            #pragma unroll
            for (int q = 0; q < 4; q++) {
                int idx = tid + q * 128;
                int row = idx >> 3, j = idx & 7;
                cp16(sA + ((c + 1) & 1) * K2_A_STAGE + row * 144 + j * 16,
                     g_B16 + abase + (size_t)row * KC + (c + 1) * 64 + j * 8);
            }
            asm volatile("cp.async.commit_group;" ::: "memory");
            asm volatile("cp.async.wait_group 1;" ::: "memory");
        } else {
            asm volatile("cp.async.wait_group 0;" ::: "memory");
        }
        __syncthreads();

        const uint32_t aStage = aBase + (c & 1) * K2_A_STAGE;
        #pragma unroll
        for (int kbl = 0; kbl < 4; kbl++) {
            uint32_t a[4];
            ldsm_x4(a, aStage + kbl * 32);
            const uint4* wf = g_Wfrag + (c * 4 + kbl) * 128 + lane;
            #pragma unroll
            for (int nb = 0; nb < 4; nb++) {
                const uint4 wv = __ldg(&wf[nb * 32]);
                mma16816(acc[nb], a, wv.x, wv.y);   // hi plane
                mma16816(acc[nb], a, wv.z, wv.w);   // lo plane
            }
        }
        __syncthreads();
    }

    // epilogue: normalize, bias, relu
    const int row0 = tile * MTILE2 + w * 16 + g;
    const int row1 = row0 + 8;
    float i0 = 0.f, i1 = 0.f;
    if (row0 < N_OUT_C) {
        float dn = g_den[row0];
        i0 = __fdividef(1.f, dn > 0.f ? dn : 1.f);
    }
    if (row1 < N_OUT_C) {
        float dn = g_den[row1];
        i1 = __fdividef(1.f, dn > 0.f ? dn : 1.f);
    }
    #pragma unroll
    for (int nb = 0; nb < 4; nb++) {
        const int c0 = nb * 8 + 2 * t;
        const float2 bb = *reinterpret_cast<const float2*>(bias + c0);
        if (row0 < N_OUT_C) {
            float2 v;
            v.x = fmaxf(acc[nb][0] * i0 + bb.x, 0.f);
            v.y = fmaxf(acc[nb][1] * i0 + bb.y, 0.f);
            *reinterpret_cast<float2*>(out + (size_t)row0 * COUT + c0) = v;
        }
        if (row1 < N_OUT_C) {
            float2 v;
            v.x = fmaxf(acc[nb][2] * i1 + bb.x, 0.f);
            v.y = fmaxf(acc[nb][3] * i1 + bb.y, 0.f);
            *reinterpret_cast<float2*>(out + (size_t)row1 * COUT + c0) = v;
        }
    }
}

// ================= host =================
extern "C" void kernel_launch(void* const* d_in, const int* in_sizes, int n_in,
                              void* d_out, int out_size)
{
    const float* feats        = (const float*)d_in[0];
    const float* inp_points   = (const float*)d_in[1];
    const float* out_points   = (const float*)d_in[2];
    const float* out_extents  = (const float*)d_in[3];
    const float* scale_compat = (const float*)d_in[4];
    const int*   nidx         = (const int*)  d_in[5];
    // d_in[6] = neighbors_row_splits: fixed degree, unused
    const float* ndist        = (const float*)d_in[7];
    const float* kernW        = (const float*)d_in[8];
    const float* bias         = (const float*)d_in[9];
    float* out = (float*)d_out;

    cudaFuncSetAttribute(k1_scatter, cudaFuncAttributeMaxDynamicSharedMemorySize,
                         (int)sizeof(Smem1));
    cudaFuncSetAttribute(k2_gemm, cudaFuncAttributeMaxDynamicSharedMemorySize,
                         K2_SMEM);

    k0_wfrag<<<32, 256>>>(kernW);
    k1_scatter<<<888, 128, sizeof(Smem1)>>>(feats, inp_points, out_points,
                                            out_extents, scale_compat, nidx, ndist);
    k2_gemm<<<NTILES2, 128, K2_SMEM>>>(out, bias);
}